// round 1
// baseline (speedup 1.0000x reference)
#include <cuda_runtime.h>

#define Bb 16
#define Cc 306
#define Tt 4096
#define Mm 270
#define Gg 64
#define TILE_T 256
#define MPAD 272

// Precomputed per-(b,c) corner indices and bilinear weights (scratch: __device__ globals)
__device__ int4   g_idx[Bb * Cc];
__device__ float4 g_w[Bb * Cc];

__global__ void precompute_kernel(const float* __restrict__ pos) {
    int i = blockIdx.x * blockDim.x + threadIdx.x;
    if (i >= Bb * Cc) return;
    float p0 = pos[2 * i + 0];
    float p1 = pos[2 * i + 1];
    // match reference: grid_pos = (p + 1) * 8 / 2
    float gp0 = (p0 + 1.0f) * 8.0f * 0.5f;
    float gp1 = (p1 + 1.0f) * 8.0f * 0.5f;
    float lo0 = floorf(gp0), lo1 = floorf(gp1);
    int il0 = (int)lo0, il1 = (int)lo1;
    int ih0 = (int)ceilf(gp0), ih1 = (int)ceilf(gp1);
    // safety clamps (inputs guaranteed in range; clamp guards OOB smem writes)
    il0 = min(7, max(0, il0)); il1 = min(7, max(0, il1));
    ih0 = min(7, max(0, ih0)); ih1 = min(7, max(0, ih1));
    float wh0 = gp0 - lo0, wl0 = 1.0f - wh0;
    float wh1 = gp1 - lo1, wl1 = 1.0f - wh1;
    // combos in reference order: (0,0),(0,1),(1,0),(1,1); idx = i0*8 + i1
    g_idx[i] = make_int4(il0 * 8 + il1, il0 * 8 + ih1, ih0 * 8 + il1, ih0 * 8 + ih1);
    g_w[i]   = make_float4(wl0 * wl1, wl0 * wh1, wh0 * wl1, wh0 * wh1);
}

// smem: gv[64][256] fp32 (64KB) + Wt[64][272] fp32 (68KB) = 132KB
#define SMEM_BYTES ((Gg * TILE_T + Gg * MPAD) * 4)

__global__ void __launch_bounds__(256, 1)
merge_kernel(const float* __restrict__ x,
             const float* __restrict__ W,
             float* __restrict__ out) {
    extern __shared__ float smem[];
    float* gv = smem;                 // [64][TILE_T]
    float* Wt = smem + Gg * TILE_T;   // [64][MPAD]  Wt[k][m] = W[m][k]

    const int tid = threadIdx.x;
    const int b   = blockIdx.y;
    const int t0  = blockIdx.x * TILE_T;

    // ---- stage W transposed into smem ----
    for (int i = tid; i < Mm * Gg; i += 256) {
        int m = i >> 6;
        int k = i & 63;
        Wt[k * MPAD + m] = W[i];
    }
    if (tid < 2 * Gg) {  // zero-pad m = 270, 271
        int k = tid >> 1;
        int m = Mm + (tid & 1);
        Wt[k * MPAD + m] = 0.0f;
    }
    // ---- zero grid accumulator ----
    for (int i = tid; i < Gg * TILE_T; i += 256) gv[i] = 0.0f;
    __syncthreads();

    // ---- phase B: scatter x into gv. thread owns column t = tid (race-free) ----
    {
        const float* xb = x + (b * Cc) * Tt + t0 + tid;
        const int4*   idxp = g_idx + b * Cc;
        const float4* wp   = g_w   + b * Cc;
        float* gvt = gv + tid;
#pragma unroll 2
        for (int c = 0; c < Cc; c++) {
            float v = xb[c * Tt];
            int4   id = idxp[c];
            float4 w  = wp[c];
            gvt[id.x * TILE_T] += v * w.x;
            gvt[id.y * TILE_T] += v * w.y;
            gvt[id.z * TILE_T] += v * w.z;
            gvt[id.w * TILE_T] += v * w.w;
        }
    }
    __syncthreads();

    // ---- phase C: out_tile[270 x 256] = W[270 x 64] @ gv[64 x 256] ----
    // thread layout: tx in [0,64) covers 4 t (float4); ty in [0,4); 4 m-chunks of 68,
    // thread computes 17 m rows per chunk. W reads warp-broadcast; gv reads LDS.128.
    const int tx = tid & 63;
    const int ty = tid >> 6;
    const float4* gvv = (const float4*)gv;  // row k at index k*64 + tx

    float* outb = out + (b * Mm) * Tt + t0 + tx * 4;

#pragma unroll 1
    for (int chunk = 0; chunk < 4; chunk++) {
        const int mbase = chunk * 68 + ty * 17;
        float4 acc[17];
#pragma unroll
        for (int i = 0; i < 17; i++) acc[i] = make_float4(0.f, 0.f, 0.f, 0.f);

#pragma unroll 4
        for (int k = 0; k < Gg; k++) {
            float4 gfrag = gvv[k * (TILE_T / 4) + tx];
            const float* wrow = Wt + k * MPAD + mbase;
#pragma unroll
            for (int i = 0; i < 17; i++) {
                float wv = wrow[i];
                acc[i].x += wv * gfrag.x;
                acc[i].y += wv * gfrag.y;
                acc[i].z += wv * gfrag.z;
                acc[i].w += wv * gfrag.w;
            }
        }
#pragma unroll
        for (int i = 0; i < 17; i++) {
            int m = mbase + i;
            if (m < Mm) {
                *(float4*)(outb + m * Tt) = acc[i];
            }
        }
    }
}

extern "C" void kernel_launch(void* const* d_in, const int* in_sizes, int n_in,
                              void* d_out, int out_size) {
    const float* x   = (const float*)d_in[0];  // [B, C, T]
    const float* pos = (const float*)d_in[1];  // [B, C, 2]
    const float* W   = (const float*)d_in[2];  // [M, G]
    float* out = (float*)d_out;                // [B, M, T]

    cudaFuncSetAttribute(merge_kernel,
                         cudaFuncAttributeMaxDynamicSharedMemorySize, SMEM_BYTES);

    precompute_kernel<<<(Bb * Cc + 255) / 256, 256>>>(pos);
    merge_kernel<<<dim3(Tt / TILE_T, Bb), 256, SMEM_BYTES>>>(x, W, out);
}

// round 3
// speedup vs baseline: 1.3806x; 1.3806x over previous
#include <cuda_runtime.h>
#include <cuda_bf16.h>
#include <cstdint>

#define Bb 16
#define Cc 306
#define Tt 4096
#define Mm 270
#define Gg 64
#define MPAD 288          // 3 m-tiles of 96
#define MT 96
#define NT 128
#define STILE 256         // scatter t-tile

// ---------------- device scratch ----------------
__device__ int4   g_idx[Bb * Cc];
__device__ float4 g_w[Bb * Cc];
__device__ __nv_bfloat16 d_Whi[MPAD * Gg];
__device__ __nv_bfloat16 d_Wlo[MPAD * Gg];
__device__ __nv_bfloat16 d_gvhi[Bb * Gg * Tt];
__device__ __nv_bfloat16 d_gvlo[Bb * Gg * Tt];

__device__ __forceinline__ uint32_t smem_u32(const void* p) {
    uint32_t a;
    asm("{ .reg .u64 t; cvta.to.shared.u64 t, %1; cvt.u32.u64 %0, t; }" : "=r"(a) : "l"(p));
    return a;
}

// ---------------- kernel 1: per-(b,c) corner indices/weights ----------------
__global__ void precompute_kernel(const float* __restrict__ pos) {
    int i = blockIdx.x * blockDim.x + threadIdx.x;
    if (i >= Bb * Cc) return;
    float gp0 = (pos[2 * i + 0] + 1.0f) * 4.0f;
    float gp1 = (pos[2 * i + 1] + 1.0f) * 4.0f;
    float lo0 = floorf(gp0), lo1 = floorf(gp1);
    int il0 = min(7, max(0, (int)lo0)), il1 = min(7, max(0, (int)lo1));
    int ih0 = min(7, max(0, (int)ceilf(gp0))), ih1 = min(7, max(0, (int)ceilf(gp1)));
    float wh0 = gp0 - lo0, wl0 = 1.0f - wh0;
    float wh1 = gp1 - lo1, wl1 = 1.0f - wh1;
    g_idx[i] = make_int4(il0 * 8 + il1, il0 * 8 + ih1, ih0 * 8 + il1, ih0 * 8 + ih1);
    g_w[i]   = make_float4(wl0 * wl1, wl0 * wh1, wh0 * wl1, wh0 * wh1);
}

// ---------------- kernel 2: split W into bf16 hi/lo, padded to MPAD ----------------
__global__ void splitw_kernel(const float* __restrict__ W) {
    int i = blockIdx.x * blockDim.x + threadIdx.x;
    if (i >= MPAD * Gg) return;
    float v = (i < Mm * Gg) ? W[i] : 0.0f;
    __nv_bfloat16 h = __float2bfloat16(v);
    d_Whi[i] = h;
    d_Wlo[i] = __float2bfloat16(v - __bfloat162float(h));
}

// ---------------- kernel 3: scatter x -> gv (fp32 smem), write bf16 splits ----------------
__global__ void __launch_bounds__(256)
scatter_kernel(const float* __restrict__ x) {
    extern __shared__ float gv[];  // [64][STILE]
    const int tid = threadIdx.x;
    const int b = blockIdx.y;
    const int t0 = blockIdx.x * STILE;

    for (int i = tid; i < Gg * STILE; i += 256) gv[i] = 0.0f;
    __syncthreads();

    {
        const float* xb = x + (size_t)(b * Cc) * Tt + t0 + tid;
        const int4*   idxp = g_idx + b * Cc;
        const float4* wp   = g_w   + b * Cc;
        float* gvt = gv + tid;
#pragma unroll 2
        for (int c = 0; c < Cc; c++) {
            float v = xb[(size_t)c * Tt];
            int4 id = idxp[c];
            float4 w = wp[c];
            gvt[id.x * STILE] += v * w.x;
            gvt[id.y * STILE] += v * w.y;
            gvt[id.z * STILE] += v * w.z;
            gvt[id.w * STILE] += v * w.w;
        }
    }
    __syncthreads();

    // convert + store splits: i covers 64 rows x 128 pairs
    uint32_t* gh = (uint32_t*)d_gvhi;
    uint32_t* gl = (uint32_t*)d_gvlo;
    for (int i = tid; i < Gg * (STILE / 2); i += 256) {
        int row = i >> 7, pair = i & 127;
        float2 v = *(float2*)&gv[row * STILE + pair * 2];
        __nv_bfloat162 h2 = __floats2bfloat162_rn(v.x, v.y);
        float hx = __bfloat162float(__low2bfloat16(h2));
        float hy = __bfloat162float(__high2bfloat16(h2));
        __nv_bfloat162 l2 = __floats2bfloat162_rn(v.x - hx, v.y - hy);
        size_t off = ((size_t)(b * Gg + row) * Tt + t0 + pair * 2) >> 1;
        gh[off] = *(uint32_t*)&h2;
        gl[off] = *(uint32_t*)&l2;
    }
}

// ---------------- kernel 4: out[b] = W @ gv[b] via mma.sync bf16 (3 split passes) ----------------
// smem: AHI [96][72] bf16, ALO same, BHI [64][136] bf16, BLO same
#define APITCH 72
#define BPITCH 136
#define SM_AHI 0
#define SM_ALO (96 * APITCH * 2)
#define SM_BHI (2 * 96 * APITCH * 2)
#define SM_BLO (SM_BHI + 64 * BPITCH * 2)
#define SM_GEMM (SM_BLO + 64 * BPITCH * 2)

__device__ __forceinline__ void ldsm_x4(uint32_t* r, uint32_t addr) {
    asm volatile("ldmatrix.sync.aligned.m8n8.x4.shared.b16 {%0,%1,%2,%3}, [%4];"
                 : "=r"(r[0]), "=r"(r[1]), "=r"(r[2]), "=r"(r[3]) : "r"(addr));
}
__device__ __forceinline__ void ldsm_x4_t(uint32_t* r, uint32_t addr) {
    asm volatile("ldmatrix.sync.aligned.m8n8.x4.trans.shared.b16 {%0,%1,%2,%3}, [%4];"
                 : "=r"(r[0]), "=r"(r[1]), "=r"(r[2]), "=r"(r[3]) : "r"(addr));
}
__device__ __forceinline__ void mma16816(float* c, const uint32_t* a, const uint32_t* b) {
    asm volatile(
        "mma.sync.aligned.m16n8k16.row.col.f32.bf16.bf16.f32 "
        "{%0,%1,%2,%3}, {%4,%5,%6,%7}, {%8,%9}, {%0,%1,%2,%3};"
        : "+f"(c[0]), "+f"(c[1]), "+f"(c[2]), "+f"(c[3])
        : "r"(a[0]), "r"(a[1]), "r"(a[2]), "r"(a[3]), "r"(b[0]), "r"(b[1]));
}

__global__ void __launch_bounds__(128)
gemm_kernel(float* __restrict__ out) {
    extern __shared__ char smem[];
    const uint32_t sb = smem_u32(smem);
    const int tid = threadIdx.x;
    const int wid = tid >> 5;
    const int lane = tid & 31;
    const int wm = wid >> 1;          // 0..1
    const int wt = wid & 1;           // 0..1

    const int t0 = blockIdx.x * NT;
    const int m0 = blockIdx.y * MT;
    const int b  = blockIdx.z;

    // ---- stage A tiles (96x64 hi+lo) ----
    const uint32_t* WhiU = (const uint32_t*)d_Whi;
    const uint32_t* WloU = (const uint32_t*)d_Wlo;
    for (int i = tid; i < 96 * 32; i += 128) {
        int row = i >> 5, cp = i & 31;
        int gidx = ((m0 + row) * Gg) / 2 + cp;
        *(uint32_t*)(smem + SM_AHI + (row * APITCH + cp * 2) * 2) = WhiU[gidx];
        *(uint32_t*)(smem + SM_ALO + (row * APITCH + cp * 2) * 2) = WloU[gidx];
    }
    // ---- stage B tiles (64k x 128t hi+lo) ----
    const uint32_t* GhiU = (const uint32_t*)d_gvhi;
    const uint32_t* GloU = (const uint32_t*)d_gvlo;
    for (int i = tid; i < 64 * 64; i += 128) {
        int row = i >> 6, cp = i & 63;
        size_t gidx = ((size_t)(b * Gg + row) * Tt + t0 + cp * 2) >> 1;
        *(uint32_t*)(smem + SM_BHI + (row * BPITCH + cp * 2) * 2) = GhiU[gidx];
        *(uint32_t*)(smem + SM_BLO + (row * BPITCH + cp * 2) * 2) = GloU[gidx];
    }
    __syncthreads();

    float acc[3][8][4];
#pragma unroll
    for (int i = 0; i < 3; i++)
#pragma unroll
        for (int j = 0; j < 8; j++)
#pragma unroll
            for (int q = 0; q < 4; q++) acc[i][j][q] = 0.0f;

    const int arow = (lane & 15);
    const int acol = (lane >> 4) * 8;

#pragma unroll
    for (int ks = 0; ks < 4; ks++) {
        const int k0 = ks * 16;
        uint32_t ahi[3][4], alo[3][4], bhi[4][4], blo[4][4];
#pragma unroll
        for (int i = 0; i < 3; i++) {
            uint32_t off = ((wm * 48 + i * 16 + arow) * APITCH + k0 + acol) * 2;
            ldsm_x4(ahi[i], sb + SM_AHI + off);
            ldsm_x4(alo[i], sb + SM_ALO + off);
        }
#pragma unroll
        for (int j2 = 0; j2 < 4; j2++) {
            uint32_t off = ((k0 + arow) * BPITCH + wt * 64 + j2 * 16 + acol) * 2;
            ldsm_x4_t(bhi[j2], sb + SM_BHI + off);
            ldsm_x4_t(blo[j2], sb + SM_BLO + off);
        }
#pragma unroll
        for (int i = 0; i < 3; i++)
#pragma unroll
            for (int j = 0; j < 8; j++) {
                const uint32_t* bh = &bhi[j >> 1][(j & 1) * 2];
                const uint32_t* bl = &blo[j >> 1][(j & 1) * 2];
                mma16816(acc[i][j], ahi[i], bh);   // hi*hi
                mma16816(acc[i][j], ahi[i], bl);   // hi*lo
                mma16816(acc[i][j], alo[i], bh);   // lo*hi
            }
    }

    // ---- epilogue ----
#pragma unroll
    for (int i = 0; i < 3; i++) {
        int mlo = m0 + wm * 48 + i * 16 + (lane >> 2);
        int mhi = mlo + 8;
#pragma unroll
        for (int j = 0; j < 8; j++) {
            int t = t0 + wt * 64 + j * 8 + (lane & 3) * 2;
            if (mlo < Mm)
                *(float2*)&out[((size_t)b * Mm + mlo) * Tt + t] =
                    make_float2(acc[i][j][0], acc[i][j][1]);
            if (mhi < Mm)
                *(float2*)&out[((size_t)b * Mm + mhi) * Tt + t] =
                    make_float2(acc[i][j][2], acc[i][j][3]);
        }
    }
}

// ---------------- launch ----------------
extern "C" void kernel_launch(void* const* d_in, const int* in_sizes, int n_in,
                              void* d_out, int out_size) {
    const float* x   = (const float*)d_in[0];  // [B, C, T]
    const float* pos = (const float*)d_in[1];  // [B, C, 2]
    const float* W   = (const float*)d_in[2];  // [M, G]
    float* out = (float*)d_out;                // [B, M, T]

    cudaFuncSetAttribute(scatter_kernel, cudaFuncAttributeMaxDynamicSharedMemorySize,
                         Gg * STILE * 4);
    cudaFuncSetAttribute(gemm_kernel, cudaFuncAttributeMaxDynamicSharedMemorySize,
                         SM_GEMM);

    precompute_kernel<<<(Bb * Cc + 255) / 256, 256>>>(pos);
    splitw_kernel<<<(MPAD * Gg + 255) / 256, 256>>>(W);
    scatter_kernel<<<dim3(Tt / STILE, Bb), 256, Gg * STILE * 4>>>(x);
    gemm_kernel<<<dim3(Tt / NT, MPAD / MT, Bb), 128, SM_GEMM>>>(out);
}

// round 4
// speedup vs baseline: 2.8935x; 2.0958x over previous
#include <cuda_runtime.h>
#include <cuda_bf16.h>
#include <cstdint>

#define Bb 16
#define Cc 306
#define Tt 4096
#define Mm 270
#define Gg 64
#define CP 320            // padded channel count (5 chunks of 64)
#define MPAD 288          // 3 m-tiles of 96
#define MT 96
#define NT 128
#define T1 256            // scatter-gemm t-tile

// ---------------- device scratch ----------------
__device__ int4   g_idx[Bb * Cc];
__device__ float4 g_w[Bb * Cc];
__device__ __nv_bfloat16 d_Shi[Bb * Gg * CP];
__device__ __nv_bfloat16 d_Slo[Bb * Gg * CP];
__device__ __nv_bfloat16 d_Whi[MPAD * Gg];
__device__ __nv_bfloat16 d_Wlo[MPAD * Gg];
__device__ __nv_bfloat16 d_gvhi[Bb * Gg * Tt];
__device__ __nv_bfloat16 d_gvlo[Bb * Gg * Tt];

__device__ __forceinline__ uint32_t smem_u32(const void* p) {
    uint32_t a;
    asm("{ .reg .u64 t; cvta.to.shared.u64 t, %1; cvt.u32.u64 %0, t; }" : "=r"(a) : "l"(p));
    return a;
}
__device__ __forceinline__ void ldsm_x4(uint32_t* r, uint32_t addr) {
    asm volatile("ldmatrix.sync.aligned.m8n8.x4.shared.b16 {%0,%1,%2,%3}, [%4];"
                 : "=r"(r[0]), "=r"(r[1]), "=r"(r[2]), "=r"(r[3]) : "r"(addr));
}
__device__ __forceinline__ void ldsm_x4_t(uint32_t* r, uint32_t addr) {
    asm volatile("ldmatrix.sync.aligned.m8n8.x4.trans.shared.b16 {%0,%1,%2,%3}, [%4];"
                 : "=r"(r[0]), "=r"(r[1]), "=r"(r[2]), "=r"(r[3]) : "r"(addr));
}
__device__ __forceinline__ void mma16816(float* c, const uint32_t* a, const uint32_t* b) {
    asm volatile(
        "mma.sync.aligned.m16n8k16.row.col.f32.bf16.bf16.f32 "
        "{%0,%1,%2,%3}, {%4,%5,%6,%7}, {%8,%9}, {%0,%1,%2,%3};"
        : "+f"(c[0]), "+f"(c[1]), "+f"(c[2]), "+f"(c[3])
        : "r"(a[0]), "r"(a[1]), "r"(a[2]), "r"(a[3]), "r"(b[0]), "r"(b[1]));
}

// ---------------- kernel 1: per-(b,c) corner indices/weights ----------------
__global__ void precompute_kernel(const float* __restrict__ pos) {
    int i = blockIdx.x * blockDim.x + threadIdx.x;
    if (i >= Bb * Cc) return;
    float gp0 = (pos[2 * i + 0] + 1.0f) * 4.0f;
    float gp1 = (pos[2 * i + 1] + 1.0f) * 4.0f;
    float lo0 = floorf(gp0), lo1 = floorf(gp1);
    int il0 = min(7, max(0, (int)lo0)), il1 = min(7, max(0, (int)lo1));
    int ih0 = min(7, max(0, (int)ceilf(gp0))), ih1 = min(7, max(0, (int)ceilf(gp1)));
    float wh0 = gp0 - lo0, wl0 = 1.0f - wh0;
    float wh1 = gp1 - lo1, wl1 = 1.0f - wh1;
    g_idx[i] = make_int4(il0 * 8 + il1, il0 * 8 + ih1, ih0 * 8 + il1, ih0 * 8 + ih1);
    g_w[i]   = make_float4(wl0 * wl1, wl0 * wh1, wh0 * wl1, wh0 * wh1);
}

// ---------------- kernel 2: build dense scatter matrix S_b (bf16 split) ----------------
__global__ void sbuild_kernel() {
    int i = blockIdx.x * blockDim.x + threadIdx.x;
    if (i >= Bb * Gg * CP) return;
    int c = i % CP;
    int cell = (i / CP) % Gg;
    int b = i / (CP * Gg);
    float s = 0.0f;
    if (c < Cc) {
        int4 id = g_idx[b * Cc + c];
        float4 w = g_w[b * Cc + c];
        if (id.x == cell) s += w.x;
        if (id.y == cell) s += w.y;
        if (id.z == cell) s += w.z;
        if (id.w == cell) s += w.w;
    }
    __nv_bfloat16 h = __float2bfloat16(s);
    d_Shi[i] = h;
    d_Slo[i] = __float2bfloat16(s - __bfloat162float(h));
}

// ---------------- kernel 3: split W into bf16 hi/lo, padded to MPAD ----------------
__global__ void splitw_kernel(const float* __restrict__ W) {
    int i = blockIdx.x * blockDim.x + threadIdx.x;
    if (i >= MPAD * Gg) return;
    float v = (i < Mm * Gg) ? W[i] : 0.0f;
    __nv_bfloat16 h = __float2bfloat16(v);
    d_Whi[i] = h;
    d_Wlo[i] = __float2bfloat16(v - __bfloat162float(h));
}

// ---------------- kernel 4: gv[b] = S_b @ x_b  (tensor-core scatter) ----------------
// smem: AHI/ALO [64][72] bf16; BHI/BLO [64][264] bf16
#define A1PITCH 72
#define B1PITCH 264
#define SM1_AHI 0
#define SM1_ALO (64 * A1PITCH * 2)
#define SM1_BHI (2 * 64 * A1PITCH * 2)
#define SM1_BLO (SM1_BHI + 64 * B1PITCH * 2)
#define SM1_TOTAL (SM1_BLO + 64 * B1PITCH * 2)

__global__ void __launch_bounds__(256, 2)
sgemm_kernel(const float* __restrict__ x) {
    extern __shared__ char smem[];
    const uint32_t sb = smem_u32(smem);
    const int tid = threadIdx.x;
    const int wid = tid >> 5;
    const int lane = tid & 31;
    const int wm = wid >> 2;          // 0..1 (m group of 32)
    const int wt = wid & 3;           // 0..3 (t group of 64)

    const int t0 = blockIdx.x * T1;
    const int b  = blockIdx.y;

    const int arow = lane & 15;
    const int acol = (lane >> 4) * 8;

    float acc[2][8][4];
#pragma unroll
    for (int i = 0; i < 2; i++)
#pragma unroll
        for (int j = 0; j < 8; j++)
#pragma unroll
            for (int q = 0; q < 4; q++) acc[i][j][q] = 0.0f;

    const uint32_t* ShiU = (const uint32_t*)d_Shi;
    const uint32_t* SloU = (const uint32_t*)d_Slo;

    for (int kc = 0; kc < 5; kc++) {
        const int c0 = kc * 64;
        // ---- stage A chunk: S_b[64 x 64] hi+lo ----
        for (int i = tid; i < 64 * 32; i += 256) {
            int r = i >> 5, cp = i & 31;
            int gidx = ((b * Gg + r) * CP + c0) / 2 + cp;
            *(uint32_t*)(smem + SM1_AHI + (r * A1PITCH + cp * 2) * 2) = ShiU[gidx];
            *(uint32_t*)(smem + SM1_ALO + (r * A1PITCH + cp * 2) * 2) = SloU[gidx];
        }
        // ---- stage B chunk: x[c0..c0+64) rows x 256 t, fp32 -> bf16 split ----
        for (int i = tid; i < 64 * 64; i += 256) {
            int r = i >> 6, q = i & 63;
            int cg = c0 + r;
            float4 v = make_float4(0.f, 0.f, 0.f, 0.f);
            if (cg < Cc)
                v = *(const float4*)(x + ((size_t)(b * Cc + cg)) * Tt + t0 + q * 4);
            __nv_bfloat162 h0 = __floats2bfloat162_rn(v.x, v.y);
            __nv_bfloat162 h1 = __floats2bfloat162_rn(v.z, v.w);
            __nv_bfloat162 l0 = __floats2bfloat162_rn(
                v.x - __bfloat162float(__low2bfloat16(h0)),
                v.y - __bfloat162float(__high2bfloat16(h0)));
            __nv_bfloat162 l1 = __floats2bfloat162_rn(
                v.z - __bfloat162float(__low2bfloat16(h1)),
                v.w - __bfloat162float(__high2bfloat16(h1)));
            uint32_t off = (r * B1PITCH + q * 4) * 2;
            *(uint32_t*)(smem + SM1_BHI + off)     = *(uint32_t*)&h0;
            *(uint32_t*)(smem + SM1_BHI + off + 4) = *(uint32_t*)&h1;
            *(uint32_t*)(smem + SM1_BLO + off)     = *(uint32_t*)&l0;
            *(uint32_t*)(smem + SM1_BLO + off + 4) = *(uint32_t*)&l1;
        }
        __syncthreads();

        // ---- mma over 4 k-steps ----
#pragma unroll
        for (int ks = 0; ks < 4; ks++) {
            const int k0 = ks * 16;
            uint32_t ahi[2][4], alo[2][4];
#pragma unroll
            for (int i = 0; i < 2; i++) {
                uint32_t off = ((wm * 32 + i * 16 + arow) * A1PITCH + k0 + acol) * 2;
                ldsm_x4(ahi[i], sb + SM1_AHI + off);
                ldsm_x4(alo[i], sb + SM1_ALO + off);
            }
#pragma unroll
            for (int j2 = 0; j2 < 4; j2++) {
                uint32_t off = ((k0 + arow) * B1PITCH + wt * 64 + j2 * 16 + acol) * 2;
                uint32_t bhi[4], blo[4];
                ldsm_x4_t(bhi, sb + SM1_BHI + off);
                ldsm_x4_t(blo, sb + SM1_BLO + off);
#pragma unroll
                for (int jh = 0; jh < 2; jh++) {
                    int j = j2 * 2 + jh;
#pragma unroll
                    for (int i = 0; i < 2; i++) {
                        mma16816(acc[i][j], ahi[i], &bhi[jh * 2]);
                        mma16816(acc[i][j], ahi[i], &blo[jh * 2]);
                        mma16816(acc[i][j], alo[i], &bhi[jh * 2]);
                    }
                }
            }
        }
        __syncthreads();
    }

    // ---- epilogue: split gv tile to bf16 hi/lo and store ----
    uint32_t* gh = (uint32_t*)d_gvhi;
    uint32_t* gl = (uint32_t*)d_gvlo;
#pragma unroll
    for (int i = 0; i < 2; i++) {
        int r0 = wm * 32 + i * 16 + (lane >> 2);
        int r1 = r0 + 8;
#pragma unroll
        for (int j = 0; j < 8; j++) {
            int t = t0 + wt * 64 + j * 8 + (lane & 3) * 2;
            __nv_bfloat162 h0 = __floats2bfloat162_rn(acc[i][j][0], acc[i][j][1]);
            __nv_bfloat162 l0 = __floats2bfloat162_rn(
                acc[i][j][0] - __bfloat162float(__low2bfloat16(h0)),
                acc[i][j][1] - __bfloat162float(__high2bfloat16(h0)));
            __nv_bfloat162 h1 = __floats2bfloat162_rn(acc[i][j][2], acc[i][j][3]);
            __nv_bfloat162 l1 = __floats2bfloat162_rn(
                acc[i][j][2] - __bfloat162float(__low2bfloat16(h1)),
                acc[i][j][3] - __bfloat162float(__high2bfloat16(h1)));
            size_t o0 = ((size_t)(b * Gg + r0) * Tt + t) >> 1;
            size_t o1 = ((size_t)(b * Gg + r1) * Tt + t) >> 1;
            gh[o0] = *(uint32_t*)&h0;
            gl[o0] = *(uint32_t*)&l0;
            gh[o1] = *(uint32_t*)&h1;
            gl[o1] = *(uint32_t*)&l1;
        }
    }
}

// ---------------- kernel 5: out[b] = W @ gv[b] (unchanged from R3) ----------------
#define APITCH 72
#define BPITCH 136
#define SM_AHI 0
#define SM_ALO (96 * APITCH * 2)
#define SM_BHI (2 * 96 * APITCH * 2)
#define SM_BLO (SM_BHI + 64 * BPITCH * 2)
#define SM_GEMM (SM_BLO + 64 * BPITCH * 2)

__global__ void __launch_bounds__(128)
gemm_kernel(float* __restrict__ out) {
    extern __shared__ char smem[];
    const uint32_t sb = smem_u32(smem);
    const int tid = threadIdx.x;
    const int wid = tid >> 5;
    const int lane = tid & 31;
    const int wm = wid >> 1;
    const int wt = wid & 1;

    const int t0 = blockIdx.x * NT;
    const int m0 = blockIdx.y * MT;
    const int b  = blockIdx.z;

    const uint32_t* WhiU = (const uint32_t*)d_Whi;
    const uint32_t* WloU = (const uint32_t*)d_Wlo;
    for (int i = tid; i < 96 * 32; i += 128) {
        int row = i >> 5, cp = i & 31;
        int gidx = ((m0 + row) * Gg) / 2 + cp;
        *(uint32_t*)(smem + SM_AHI + (row * APITCH + cp * 2) * 2) = WhiU[gidx];
        *(uint32_t*)(smem + SM_ALO + (row * APITCH + cp * 2) * 2) = WloU[gidx];
    }
    const uint32_t* GhiU = (const uint32_t*)d_gvhi;
    const uint32_t* GloU = (const uint32_t*)d_gvlo;
    for (int i = tid; i < 64 * 64; i += 128) {
        int row = i >> 6, cp = i & 63;
        size_t gidx = ((size_t)(b * Gg + row) * Tt + t0 + cp * 2) >> 1;
        *(uint32_t*)(smem + SM_BHI + (row * BPITCH + cp * 2) * 2) = GhiU[gidx];
        *(uint32_t*)(smem + SM_BLO + (row * BPITCH + cp * 2) * 2) = GloU[gidx];
    }
    __syncthreads();

    float acc[3][8][4];
#pragma unroll
    for (int i = 0; i < 3; i++)
#pragma unroll
        for (int j = 0; j < 8; j++)
#pragma unroll
            for (int q = 0; q < 4; q++) acc[i][j][q] = 0.0f;

    const int arow = (lane & 15);
    const int acol = (lane >> 4) * 8;

#pragma unroll
    for (int ks = 0; ks < 4; ks++) {
        const int k0 = ks * 16;
        uint32_t ahi[3][4], alo[3][4], bhi[4][4], blo[4][4];
#pragma unroll
        for (int i = 0; i < 3; i++) {
            uint32_t off = ((wm * 48 + i * 16 + arow) * APITCH + k0 + acol) * 2;
            ldsm_x4(ahi[i], sb + SM_AHI + off);
            ldsm_x4(alo[i], sb + SM_ALO + off);
        }
#pragma unroll
        for (int j2 = 0; j2 < 4; j2++) {
            uint32_t off = ((k0 + arow) * BPITCH + wt * 64 + j2 * 16 + acol) * 2;
            ldsm_x4_t(bhi[j2], sb + SM_BHI + off);
            ldsm_x4_t(blo[j2], sb + SM_BLO + off);
        }
#pragma unroll
        for (int i = 0; i < 3; i++)
#pragma unroll
            for (int j = 0; j < 8; j++) {
                const uint32_t* bh = &bhi[j >> 1][(j & 1) * 2];
                const uint32_t* bl = &blo[j >> 1][(j & 1) * 2];
                mma16816(acc[i][j], ahi[i], bh);
                mma16816(acc[i][j], ahi[i], bl);
                mma16816(acc[i][j], alo[i], bh);
            }
    }

#pragma unroll
    for (int i = 0; i < 3; i++) {
        int mlo = m0 + wm * 48 + i * 16 + (lane >> 2);
        int mhi = mlo + 8;
#pragma unroll
        for (int j = 0; j < 8; j++) {
            int t = t0 + wt * 64 + j * 8 + (lane & 3) * 2;
            if (mlo < Mm)
                *(float2*)&out[((size_t)b * Mm + mlo) * Tt + t] =
                    make_float2(acc[i][j][0], acc[i][j][1]);
            if (mhi < Mm)
                *(float2*)&out[((size_t)b * Mm + mhi) * Tt + t] =
                    make_float2(acc[i][j][2], acc[i][j][3]);
        }
    }
}

// ---------------- launch ----------------
extern "C" void kernel_launch(void* const* d_in, const int* in_sizes, int n_in,
                              void* d_out, int out_size) {
    const float* x   = (const float*)d_in[0];  // [B, C, T]
    const float* pos = (const float*)d_in[1];  // [B, C, 2]
    const float* W   = (const float*)d_in[2];  // [M, G]
    float* out = (float*)d_out;                // [B, M, T]

    cudaFuncSetAttribute(sgemm_kernel, cudaFuncAttributeMaxDynamicSharedMemorySize, SM1_TOTAL);
    cudaFuncSetAttribute(gemm_kernel, cudaFuncAttributeMaxDynamicSharedMemorySize, SM_GEMM);

    precompute_kernel<<<(Bb * Cc + 255) / 256, 256>>>(pos);
    sbuild_kernel<<<(Bb * Gg * CP + 255) / 256, 256>>>();
    splitw_kernel<<<(MPAD * Gg + 255) / 256, 256>>>(W);
    sgemm_kernel<<<dim3(Tt / T1, Bb), 256, SM1_TOTAL>>>(x);
    gemm_kernel<<<dim3(Tt / NT, MPAD / MT, Bb), 128, SM_GEMM>>>(out);
}

// round 5
// speedup vs baseline: 3.2851x; 1.1353x over previous
#include <cuda_runtime.h>
#include <cuda_bf16.h>
#include <cstdint>

#define Bb 16
#define Cc 306
#define Tt 4096
#define Mm 270
#define Gg 64
#define CP 320            // padded channel count (5 chunks of 64)
#define MPAD 288          // 3 m-chunks of 96
#define TT 128            // t-tile per CTA

// ---------------- device scratch ----------------
__device__ int4   g_idx[Bb * Cc];
__device__ float4 g_w[Bb * Cc];
__device__ __nv_bfloat16 d_Shi[Bb * Gg * CP];
__device__ __nv_bfloat16 d_Slo[Bb * Gg * CP];
__device__ __nv_bfloat16 d_Whi[MPAD * Gg];
__device__ __nv_bfloat16 d_Wlo[MPAD * Gg];

__device__ __forceinline__ uint32_t smem_u32(const void* p) {
    uint32_t a;
    asm("{ .reg .u64 t; cvta.to.shared.u64 t, %1; cvt.u32.u64 %0, t; }" : "=r"(a) : "l"(p));
    return a;
}
__device__ __forceinline__ void ldsm_x4(uint32_t* r, uint32_t addr) {
    asm volatile("ldmatrix.sync.aligned.m8n8.x4.shared.b16 {%0,%1,%2,%3}, [%4];"
                 : "=r"(r[0]), "=r"(r[1]), "=r"(r[2]), "=r"(r[3]) : "r"(addr));
}
__device__ __forceinline__ void ldsm_x4_t(uint32_t* r, uint32_t addr) {
    asm volatile("ldmatrix.sync.aligned.m8n8.x4.trans.shared.b16 {%0,%1,%2,%3}, [%4];"
                 : "=r"(r[0]), "=r"(r[1]), "=r"(r[2]), "=r"(r[3]) : "r"(addr));
}
__device__ __forceinline__ void mma16816(float* c, const uint32_t* a, const uint32_t* b) {
    asm volatile(
        "mma.sync.aligned.m16n8k16.row.col.f32.bf16.bf16.f32 "
        "{%0,%1,%2,%3}, {%4,%5,%6,%7}, {%8,%9}, {%0,%1,%2,%3};"
        : "+f"(c[0]), "+f"(c[1]), "+f"(c[2]), "+f"(c[3])
        : "r"(a[0]), "r"(a[1]), "r"(a[2]), "r"(a[3]), "r"(b[0]), "r"(b[1]));
}

// ---------------- setup kernels ----------------
__global__ void precompute_kernel(const float* __restrict__ pos) {
    int i = blockIdx.x * blockDim.x + threadIdx.x;
    if (i >= Bb * Cc) return;
    float gp0 = (pos[2 * i + 0] + 1.0f) * 4.0f;
    float gp1 = (pos[2 * i + 1] + 1.0f) * 4.0f;
    float lo0 = floorf(gp0), lo1 = floorf(gp1);
    int il0 = min(7, max(0, (int)lo0)), il1 = min(7, max(0, (int)lo1));
    int ih0 = min(7, max(0, (int)ceilf(gp0))), ih1 = min(7, max(0, (int)ceilf(gp1)));
    float wh0 = gp0 - lo0, wl0 = 1.0f - wh0;
    float wh1 = gp1 - lo1, wl1 = 1.0f - wh1;
    g_idx[i] = make_int4(il0 * 8 + il1, il0 * 8 + ih1, ih0 * 8 + il1, ih0 * 8 + ih1);
    g_w[i]   = make_float4(wl0 * wl1, wl0 * wh1, wh0 * wl1, wh0 * wh1);
}

__global__ void sbuild_kernel() {
    int i = blockIdx.x * blockDim.x + threadIdx.x;
    if (i >= Bb * Gg * CP) return;
    int c = i % CP;
    int cell = (i / CP) % Gg;
    int b = i / (CP * Gg);
    float s = 0.0f;
    if (c < Cc) {
        int4 id = g_idx[b * Cc + c];
        float4 w = g_w[b * Cc + c];
        if (id.x == cell) s += w.x;
        if (id.y == cell) s += w.y;
        if (id.z == cell) s += w.z;
        if (id.w == cell) s += w.w;
    }
    __nv_bfloat16 h = __float2bfloat16(s);
    d_Shi[i] = h;
    d_Slo[i] = __float2bfloat16(s - __bfloat162float(h));
}

__global__ void splitw_kernel(const float* __restrict__ W) {
    int i = blockIdx.x * blockDim.x + threadIdx.x;
    if (i >= MPAD * Gg) return;
    float v = (i < Mm * Gg) ? W[i] : 0.0f;
    __nv_bfloat16 h = __float2bfloat16(v);
    d_Whi[i] = h;
    d_Wlo[i] = __float2bfloat16(v - __bfloat162float(h));
}

// ---------------- fused kernel ----------------
// smem (bytes):
//  region X (phase1 staging / phase2 W tiles):
//    SM_A1HI 0      [64][72]  bf16  9216
//    SM_A1LO 9216   [64][72]        9216
//    SM_B1HI 18432  [64][136]       17408
//    SM_B1LO 35840  [64][136]       17408   (X total 53248)
//    phase2 overlay: SM_WHI 0 [96][72] 13824; SM_WLO 13824 [96][72]
//  region Y (gv, persists):
//    SM_GVHI 53248  [64][136]       17408
//    SM_GVLO 70656  [64][136]       17408
#define A1PITCH 72
#define B1PITCH 136
#define GPITCH  136
#define WPITCH  72
#define SM_A1HI 0
#define SM_A1LO 9216
#define SM_B1HI 18432
#define SM_B1LO 35840
#define SM_WHI  0
#define SM_WLO  13824
#define SM_GVHI 53248
#define SM_GVLO 70656
#define SM_TOTAL 88064

__global__ void __launch_bounds__(256, 2)
fused_kernel(const float* __restrict__ x, float* __restrict__ out) {
    extern __shared__ char smem[];
    const uint32_t sb = smem_u32(smem);
    const int tid = threadIdx.x;
    const int wid = tid >> 5;
    const int lane = tid & 31;

    const int t0 = blockIdx.x * TT;
    const int b  = blockIdx.y;

    const int arow = lane & 15;
    const int acol = (lane >> 4) * 8;

    // ======== phase 1: gv[64 x 128] = S_b @ x_tile (3-pass bf16 split) ========
    const int wm1 = wid >> 2;     // 0..1 -> 32 m-rows
    const int wt1 = wid & 3;      // 0..3 -> 32 t-cols

    float gacc[2][4][4];
#pragma unroll
    for (int i = 0; i < 2; i++)
#pragma unroll
        for (int j = 0; j < 4; j++)
#pragma unroll
            for (int q = 0; q < 4; q++) gacc[i][j][q] = 0.0f;

    const uint32_t* ShiU = (const uint32_t*)d_Shi;
    const uint32_t* SloU = (const uint32_t*)d_Slo;

    for (int kc = 0; kc < 5; kc++) {
        const int c0 = kc * 64;
        // stage S chunk [64 x 64] hi/lo
        for (int i = tid; i < 64 * 32; i += 256) {
            int r = i >> 5, cp = i & 31;
            int gidx = ((b * Gg + r) * CP + c0) / 2 + cp;
            *(uint32_t*)(smem + SM_A1HI + (r * A1PITCH + cp * 2) * 2) = ShiU[gidx];
            *(uint32_t*)(smem + SM_A1LO + (r * A1PITCH + cp * 2) * 2) = SloU[gidx];
        }
        // stage x chunk [64 x 128] fp32 -> bf16 split
        for (int i = tid; i < 64 * 32; i += 256) {
            int r = i >> 5, q = i & 31;
            int cg = c0 + r;
            float4 v = make_float4(0.f, 0.f, 0.f, 0.f);
            if (cg < Cc)
                v = *(const float4*)(x + ((size_t)(b * Cc + cg)) * Tt + t0 + q * 4);
            __nv_bfloat162 h0 = __floats2bfloat162_rn(v.x, v.y);
            __nv_bfloat162 h1 = __floats2bfloat162_rn(v.z, v.w);
            __nv_bfloat162 l0 = __floats2bfloat162_rn(
                v.x - __bfloat162float(__low2bfloat16(h0)),
                v.y - __bfloat162float(__high2bfloat16(h0)));
            __nv_bfloat162 l1 = __floats2bfloat162_rn(
                v.z - __bfloat162float(__low2bfloat16(h1)),
                v.w - __bfloat162float(__high2bfloat16(h1)));
            uint32_t off = (r * B1PITCH + q * 4) * 2;
            *(uint32_t*)(smem + SM_B1HI + off)     = *(uint32_t*)&h0;
            *(uint32_t*)(smem + SM_B1HI + off + 4) = *(uint32_t*)&h1;
            *(uint32_t*)(smem + SM_B1LO + off)     = *(uint32_t*)&l0;
            *(uint32_t*)(smem + SM_B1LO + off + 4) = *(uint32_t*)&l1;
        }
        __syncthreads();

#pragma unroll
        for (int ks = 0; ks < 4; ks++) {
            const int k0 = ks * 16;
            uint32_t ahi[2][4], alo[2][4];
#pragma unroll
            for (int i = 0; i < 2; i++) {
                uint32_t off = ((wm1 * 32 + i * 16 + arow) * A1PITCH + k0 + acol) * 2;
                ldsm_x4(ahi[i], sb + SM_A1HI + off);
                ldsm_x4(alo[i], sb + SM_A1LO + off);
            }
#pragma unroll
            for (int j2 = 0; j2 < 2; j2++) {
                uint32_t off = ((k0 + arow) * B1PITCH + wt1 * 32 + j2 * 16 + acol) * 2;
                uint32_t bhi[4], blo[4];
                ldsm_x4_t(bhi, sb + SM_B1HI + off);
                ldsm_x4_t(blo, sb + SM_B1LO + off);
#pragma unroll
                for (int jh = 0; jh < 2; jh++) {
                    int j = j2 * 2 + jh;
#pragma unroll
                    for (int i = 0; i < 2; i++) {
                        mma16816(gacc[i][j], ahi[i], &bhi[jh * 2]);
                        mma16816(gacc[i][j], ahi[i], &blo[jh * 2]);
                        mma16816(gacc[i][j], alo[i], &bhi[jh * 2]);
                    }
                }
            }
        }
        __syncthreads();
    }

    // ======== phase 1.5: split gv fragments into smem (region Y) ========
#pragma unroll
    for (int i = 0; i < 2; i++) {
        int r0 = wm1 * 32 + i * 16 + (lane >> 2);
        int r1 = r0 + 8;
#pragma unroll
        for (int j = 0; j < 4; j++) {
            int t = wt1 * 32 + j * 8 + (lane & 3) * 2;
            __nv_bfloat162 h0 = __floats2bfloat162_rn(gacc[i][j][0], gacc[i][j][1]);
            __nv_bfloat162 l0 = __floats2bfloat162_rn(
                gacc[i][j][0] - __bfloat162float(__low2bfloat16(h0)),
                gacc[i][j][1] - __bfloat162float(__high2bfloat16(h0)));
            __nv_bfloat162 h1 = __floats2bfloat162_rn(gacc[i][j][2], gacc[i][j][3]);
            __nv_bfloat162 l1 = __floats2bfloat162_rn(
                gacc[i][j][2] - __bfloat162float(__low2bfloat16(h1)),
                gacc[i][j][3] - __bfloat162float(__high2bfloat16(h1)));
            *(uint32_t*)(smem + SM_GVHI + (r0 * GPITCH + t) * 2) = *(uint32_t*)&h0;
            *(uint32_t*)(smem + SM_GVLO + (r0 * GPITCH + t) * 2) = *(uint32_t*)&l0;
            *(uint32_t*)(smem + SM_GVHI + (r1 * GPITCH + t) * 2) = *(uint32_t*)&h1;
            *(uint32_t*)(smem + SM_GVLO + (r1 * GPITCH + t) * 2) = *(uint32_t*)&l1;
        }
    }

    // ======== phase 2: out[mc*96..][t0..] = W_chunk @ gv ========
    const int wm2 = wid >> 2;     // 0..1 -> 48 m-rows
    const int wt2 = wid & 3;      // 0..3 -> 32 t-cols
    const uint32_t* WhiU = (const uint32_t*)d_Whi;
    const uint32_t* WloU = (const uint32_t*)d_Wlo;

    for (int mc = 0; mc < 3; mc++) {
        const int m0 = mc * 96;
        // stage W chunk [96 x 64] hi/lo into region X (overlay)
        __syncthreads();   // protect X (phase1 ldsm done / prev iter ldsm done) + Y writes visible
        for (int i = tid; i < 96 * 32; i += 256) {
            int r = i >> 5, cp = i & 31;
            int gidx = ((m0 + r) * Gg) / 2 + cp;
            *(uint32_t*)(smem + SM_WHI + (r * WPITCH + cp * 2) * 2) = WhiU[gidx];
            *(uint32_t*)(smem + SM_WLO + (r * WPITCH + cp * 2) * 2) = WloU[gidx];
        }
        __syncthreads();

        float acc[3][4][4];
#pragma unroll
        for (int i = 0; i < 3; i++)
#pragma unroll
            for (int j = 0; j < 4; j++)
#pragma unroll
                for (int q = 0; q < 4; q++) acc[i][j][q] = 0.0f;

#pragma unroll
        for (int ks = 0; ks < 4; ks++) {
            const int k0 = ks * 16;
            uint32_t ahi[3][4], alo[3][4];
#pragma unroll
            for (int i = 0; i < 3; i++) {
                uint32_t off = ((wm2 * 48 + i * 16 + arow) * WPITCH + k0 + acol) * 2;
                ldsm_x4(ahi[i], sb + SM_WHI + off);
                ldsm_x4(alo[i], sb + SM_WLO + off);
            }
#pragma unroll
            for (int j2 = 0; j2 < 2; j2++) {
                uint32_t off = ((k0 + arow) * GPITCH + wt2 * 32 + j2 * 16 + acol) * 2;
                uint32_t bhi[4], blo[4];
                ldsm_x4_t(bhi, sb + SM_GVHI + off);
                ldsm_x4_t(blo, sb + SM_GVLO + off);
#pragma unroll
                for (int jh = 0; jh < 2; jh++) {
                    int j = j2 * 2 + jh;
#pragma unroll
                    for (int i = 0; i < 3; i++) {
                        mma16816(acc[i][j], ahi[i], &bhi[jh * 2]);
                        mma16816(acc[i][j], ahi[i], &blo[jh * 2]);
                        mma16816(acc[i][j], alo[i], &bhi[jh * 2]);
                    }
                }
            }
        }

        // epilogue: store out chunk
#pragma unroll
        for (int i = 0; i < 3; i++) {
            int mlo = m0 + wm2 * 48 + i * 16 + (lane >> 2);
            int mhi = mlo + 8;
#pragma unroll
            for (int j = 0; j < 4; j++) {
                int t = t0 + wt2 * 32 + j * 8 + (lane & 3) * 2;
                if (mlo < Mm)
                    *(float2*)&out[((size_t)b * Mm + mlo) * Tt + t] =
                        make_float2(acc[i][j][0], acc[i][j][1]);
                if (mhi < Mm)
                    *(float2*)&out[((size_t)b * Mm + mhi) * Tt + t] =
                        make_float2(acc[i][j][2], acc[i][j][3]);
            }
        }
    }
}

// ---------------- launch ----------------
extern "C" void kernel_launch(void* const* d_in, const int* in_sizes, int n_in,
                              void* d_out, int out_size) {
    const float* x   = (const float*)d_in[0];  // [B, C, T]
    const float* pos = (const float*)d_in[1];  // [B, C, 2]
    const float* W   = (const float*)d_in[2];  // [M, G]
    float* out = (float*)d_out;                // [B, M, T]

    cudaFuncSetAttribute(fused_kernel, cudaFuncAttributeMaxDynamicSharedMemorySize, SM_TOTAL);

    precompute_kernel<<<(Bb * Cc + 255) / 256, 256>>>(pos);
    sbuild_kernel<<<(Bb * Gg * CP + 255) / 256, 256>>>();
    splitw_kernel<<<(MPAD * Gg + 255) / 256, 256>>>(W);
    fused_kernel<<<dim3(Tt / TT, Bb), 256, SM_TOTAL>>>(x, out);
}

// round 6
// speedup vs baseline: 3.8791x; 1.1808x over previous
#include <cuda_runtime.h>
#include <cuda_bf16.h>
#include <cstdint>

#define Bb 16
#define Cc 306
#define Tt 4096
#define Mm 270
#define Gg 64
#define CP 320            // padded channel count (5 chunks of 64)
#define MPAD 288          // 3 m-chunks of 96
#define TT 128            // t-tile per CTA

// ---------------- device scratch ----------------
__device__ int4   g_idx[Bb * Cc];
__device__ float4 g_w[Bb * Cc];
__device__ __nv_bfloat16 d_Shi[Bb * Gg * CP];
__device__ __nv_bfloat16 d_Slo[Bb * Gg * CP];
__device__ __nv_bfloat16 d_Whi[MPAD * Gg];
__device__ __nv_bfloat16 d_Wlo[MPAD * Gg];

__device__ __forceinline__ uint32_t smem_u32(const void* p) {
    uint32_t a;
    asm("{ .reg .u64 t; cvta.to.shared.u64 t, %1; cvt.u32.u64 %0, t; }" : "=r"(a) : "l"(p));
    return a;
}
__device__ __forceinline__ void ldsm_x4(uint32_t* r, uint32_t addr) {
    asm volatile("ldmatrix.sync.aligned.m8n8.x4.shared.b16 {%0,%1,%2,%3}, [%4];"
                 : "=r"(r[0]), "=r"(r[1]), "=r"(r[2]), "=r"(r[3]) : "r"(addr));
}
__device__ __forceinline__ void ldsm_x4_t(uint32_t* r, uint32_t addr) {
    asm volatile("ldmatrix.sync.aligned.m8n8.x4.trans.shared.b16 {%0,%1,%2,%3}, [%4];"
                 : "=r"(r[0]), "=r"(r[1]), "=r"(r[2]), "=r"(r[3]) : "r"(addr));
}
__device__ __forceinline__ void mma16816(float* c, const uint32_t* a, const uint32_t* b) {
    asm volatile(
        "mma.sync.aligned.m16n8k16.row.col.f32.bf16.bf16.f32 "
        "{%0,%1,%2,%3}, {%4,%5,%6,%7}, {%8,%9}, {%0,%1,%2,%3};"
        : "+f"(c[0]), "+f"(c[1]), "+f"(c[2]), "+f"(c[3])
        : "r"(a[0]), "r"(a[1]), "r"(a[2]), "r"(a[3]), "r"(b[0]), "r"(b[1]));
}

// ---------------- setup kernels ----------------
__global__ void precompute_kernel(const float* __restrict__ pos) {
    int i = blockIdx.x * blockDim.x + threadIdx.x;
    if (i >= Bb * Cc) return;
    float gp0 = (pos[2 * i + 0] + 1.0f) * 4.0f;
    float gp1 = (pos[2 * i + 1] + 1.0f) * 4.0f;
    float lo0 = floorf(gp0), lo1 = floorf(gp1);
    int il0 = min(7, max(0, (int)lo0)), il1 = min(7, max(0, (int)lo1));
    int ih0 = min(7, max(0, (int)ceilf(gp0))), ih1 = min(7, max(0, (int)ceilf(gp1)));
    float wh0 = gp0 - lo0, wl0 = 1.0f - wh0;
    float wh1 = gp1 - lo1, wl1 = 1.0f - wh1;
    g_idx[i] = make_int4(il0 * 8 + il1, il0 * 8 + ih1, ih0 * 8 + il1, ih0 * 8 + ih1);
    g_w[i]   = make_float4(wl0 * wl1, wl0 * wh1, wh0 * wl1, wh0 * wh1);
}

__global__ void sbuild_kernel() {
    int i = blockIdx.x * blockDim.x + threadIdx.x;
    if (i >= Bb * Gg * CP) return;
    int c = i % CP;
    int cell = (i / CP) % Gg;
    int b = i / (CP * Gg);
    float s = 0.0f;
    if (c < Cc) {
        int4 id = g_idx[b * Cc + c];
        float4 w = g_w[b * Cc + c];
        if (id.x == cell) s += w.x;
        if (id.y == cell) s += w.y;
        if (id.z == cell) s += w.z;
        if (id.w == cell) s += w.w;
    }
    __nv_bfloat16 h = __float2bfloat16(s);
    d_Shi[i] = h;
    d_Slo[i] = __float2bfloat16(s - __bfloat162float(h));
}

__global__ void splitw_kernel(const float* __restrict__ W) {
    int i = blockIdx.x * blockDim.x + threadIdx.x;
    if (i >= MPAD * Gg) return;
    float v = (i < Mm * Gg) ? W[i] : 0.0f;
    __nv_bfloat16 h = __float2bfloat16(v);
    d_Whi[i] = h;
    d_Wlo[i] = __float2bfloat16(v - __bfloat162float(h));
}

// ---------------- fused kernel (register-prefetch pipelined) ----------------
#define A1PITCH 72
#define B1PITCH 136
#define GPITCH  136
#define WPITCH  72
#define SM_A1HI 0
#define SM_A1LO 9216
#define SM_B1HI 18432
#define SM_B1LO 35840
#define SM_WHI  0
#define SM_WLO  13824
#define SM_GVHI 53248
#define SM_GVLO 70656
#define SM_TOTAL 88064

__global__ void __launch_bounds__(256, 1)
fused_kernel(const float* __restrict__ x, float* __restrict__ out) {
    extern __shared__ char smem[];
    const uint32_t sb = smem_u32(smem);
    const int tid = threadIdx.x;
    const int wid = tid >> 5;
    const int lane = tid & 31;

    const int t0 = blockIdx.x * TT;
    const int b  = blockIdx.y;

    const int arow = lane & 15;
    const int acol = (lane >> 4) * 8;

    const uint32_t* ShiU = (const uint32_t*)d_Shi;
    const uint32_t* SloU = (const uint32_t*)d_Slo;

    // ======== phase 1: gv[64 x 128] = S_b @ x_tile (3-pass bf16 split) ========
    const int wm1 = wid >> 2;     // 0..1 -> 32 m-rows
    const int wt1 = wid & 3;      // 0..3 -> 32 t-cols

    float gacc[2][4][4];
#pragma unroll
    for (int i = 0; i < 2; i++)
#pragma unroll
        for (int j = 0; j < 4; j++)
#pragma unroll
            for (int q = 0; q < 4; q++) gacc[i][j][q] = 0.0f;

    // prefetch registers for current chunk
    uint32_t sHi[8], sLo[8];
    float4 xv[8];

    // each thread owns rows r = wid + 8*it, column lane (S) / float4 col lane (x)
    auto load_S = [&](int c0) {
#pragma unroll
        for (int it = 0; it < 8; it++) {
            int r = wid + 8 * it;
            int gidx = ((b * Gg + r) * CP + c0) / 2 + lane;
            sHi[it] = ShiU[gidx];
            sLo[it] = SloU[gidx];
        }
    };
    auto load_X = [&](int c0) {
#pragma unroll
        for (int it = 0; it < 8; it++) {
            int cg = c0 + wid + 8 * it;
            xv[it] = (cg < Cc)
                ? *(const float4*)(x + ((size_t)(b * Cc + cg)) * Tt + t0 + lane * 4)
                : make_float4(0.f, 0.f, 0.f, 0.f);
        }
    };

    load_S(0);
    load_X(0);

    for (int kc = 0; kc < 5; kc++) {
        __syncthreads();   // prior MMA done before overwriting staging
        // ---- STS current chunk from registers ----
#pragma unroll
        for (int it = 0; it < 8; it++) {
            int r = wid + 8 * it;
            uint32_t aoff = (r * A1PITCH + lane * 2) * 2;
            *(uint32_t*)(smem + SM_A1HI + aoff) = sHi[it];
            *(uint32_t*)(smem + SM_A1LO + aoff) = sLo[it];

            float4 v = xv[it];
            __nv_bfloat162 h0 = __floats2bfloat162_rn(v.x, v.y);
            __nv_bfloat162 h1 = __floats2bfloat162_rn(v.z, v.w);
            __nv_bfloat162 l0 = __floats2bfloat162_rn(
                v.x - __bfloat162float(__low2bfloat16(h0)),
                v.y - __bfloat162float(__high2bfloat16(h0)));
            __nv_bfloat162 l1 = __floats2bfloat162_rn(
                v.z - __bfloat162float(__low2bfloat16(h1)),
                v.w - __bfloat162float(__high2bfloat16(h1)));
            uint32_t boff = (r * B1PITCH + lane * 4) * 2;
            *(uint32_t*)(smem + SM_B1HI + boff)     = *(uint32_t*)&h0;
            *(uint32_t*)(smem + SM_B1HI + boff + 4) = *(uint32_t*)&h1;
            *(uint32_t*)(smem + SM_B1LO + boff)     = *(uint32_t*)&l0;
            *(uint32_t*)(smem + SM_B1LO + boff + 4) = *(uint32_t*)&l1;
        }
        __syncthreads();

        // ---- issue next-chunk loads; latency hidden under MMA below ----
        if (kc < 4) {
            load_S((kc + 1) * 64);
            load_X((kc + 1) * 64);
        }

        // ---- MMA on staged chunk ----
#pragma unroll
        for (int ks = 0; ks < 4; ks++) {
            const int k0 = ks * 16;
            uint32_t ahi[2][4], alo[2][4];
#pragma unroll
            for (int i = 0; i < 2; i++) {
                uint32_t off = ((wm1 * 32 + i * 16 + arow) * A1PITCH + k0 + acol) * 2;
                ldsm_x4(ahi[i], sb + SM_A1HI + off);
                ldsm_x4(alo[i], sb + SM_A1LO + off);
            }
#pragma unroll
            for (int j2 = 0; j2 < 2; j2++) {
                uint32_t off = ((k0 + arow) * B1PITCH + wt1 * 32 + j2 * 16 + acol) * 2;
                uint32_t bhi[4], blo[4];
                ldsm_x4_t(bhi, sb + SM_B1HI + off);
                ldsm_x4_t(blo, sb + SM_B1LO + off);
#pragma unroll
                for (int jh = 0; jh < 2; jh++) {
                    int j = j2 * 2 + jh;
#pragma unroll
                    for (int i = 0; i < 2; i++) {
                        mma16816(gacc[i][j], ahi[i], &bhi[jh * 2]);
                        mma16816(gacc[i][j], ahi[i], &blo[jh * 2]);
                        mma16816(gacc[i][j], alo[i], &bhi[jh * 2]);
                    }
                }
            }
        }
    }

    // ======== prefetch W chunk 0 (overlaps gv split below) ========
    const uint32_t* WhiU = (const uint32_t*)d_Whi;
    const uint32_t* WloU = (const uint32_t*)d_Wlo;
    uint32_t wHi[12], wLo[12];
    auto load_W = [&](int m0) {
#pragma unroll
        for (int it = 0; it < 12; it++) {
            int r = wid + 8 * it;
            int gidx = ((m0 + r) * Gg) / 2 + lane;
            wHi[it] = WhiU[gidx];
            wLo[it] = WloU[gidx];
        }
    };
    load_W(0);

    // ======== phase 1.5: split gv fragments into smem (region Y) ========
#pragma unroll
    for (int i = 0; i < 2; i++) {
        int r0 = wm1 * 32 + i * 16 + (lane >> 2);
        int r1 = r0 + 8;
#pragma unroll
        for (int j = 0; j < 4; j++) {
            int t = wt1 * 32 + j * 8 + (lane & 3) * 2;
            __nv_bfloat162 h0 = __floats2bfloat162_rn(gacc[i][j][0], gacc[i][j][1]);
            __nv_bfloat162 l0 = __floats2bfloat162_rn(
                gacc[i][j][0] - __bfloat162float(__low2bfloat16(h0)),
                gacc[i][j][1] - __bfloat162float(__high2bfloat16(h0)));
            __nv_bfloat162 h1 = __floats2bfloat162_rn(gacc[i][j][2], gacc[i][j][3]);
            __nv_bfloat162 l1 = __floats2bfloat162_rn(
                gacc[i][j][2] - __bfloat162float(__low2bfloat16(h1)),
                gacc[i][j][3] - __bfloat162float(__high2bfloat16(h1)));
            *(uint32_t*)(smem + SM_GVHI + (r0 * GPITCH + t) * 2) = *(uint32_t*)&h0;
            *(uint32_t*)(smem + SM_GVLO + (r0 * GPITCH + t) * 2) = *(uint32_t*)&l0;
            *(uint32_t*)(smem + SM_GVHI + (r1 * GPITCH + t) * 2) = *(uint32_t*)&h1;
            *(uint32_t*)(smem + SM_GVLO + (r1 * GPITCH + t) * 2) = *(uint32_t*)&l1;
        }
    }

    // ======== phase 2: out[mc*96..][t0..] = W_chunk @ gv ========
    const int wm2 = wid >> 2;     // 0..1 -> 48 m-rows
    const int wt2 = wid & 3;      // 0..3 -> 32 t-cols

    for (int mc = 0; mc < 3; mc++) {
        const int m0 = mc * 96;
        __syncthreads();   // X free (prior ldsm done) + Y writes visible (mc==0)
#pragma unroll
        for (int it = 0; it < 12; it++) {
            int r = wid + 8 * it;
            uint32_t off = (r * WPITCH + lane * 2) * 2;
            *(uint32_t*)(smem + SM_WHI + off) = wHi[it];
            *(uint32_t*)(smem + SM_WLO + off) = wLo[it];
        }
        __syncthreads();

        if (mc < 2) load_W((mc + 1) * 96);   // hidden under MMA below

        float acc[3][4][4];
#pragma unroll
        for (int i = 0; i < 3; i++)
#pragma unroll
            for (int j = 0; j < 4; j++)
#pragma unroll
                for (int q = 0; q < 4; q++) acc[i][j][q] = 0.0f;

#pragma unroll
        for (int ks = 0; ks < 4; ks++) {
            const int k0 = ks * 16;
            uint32_t ahi[3][4], alo[3][4];
#pragma unroll
            for (int i = 0; i < 3; i++) {
                uint32_t off = ((wm2 * 48 + i * 16 + arow) * WPITCH + k0 + acol) * 2;
                ldsm_x4(ahi[i], sb + SM_WHI + off);
                ldsm_x4(alo[i], sb + SM_WLO + off);
            }
#pragma unroll
            for (int j2 = 0; j2 < 2; j2++) {
                uint32_t off = ((k0 + arow) * GPITCH + wt2 * 32 + j2 * 16 + acol) * 2;
                uint32_t bhi[4], blo[4];
                ldsm_x4_t(bhi, sb + SM_GVHI + off);
                ldsm_x4_t(blo, sb + SM_GVLO + off);
#pragma unroll
                for (int jh = 0; jh < 2; jh++) {
                    int j = j2 * 2 + jh;
#pragma unroll
                    for (int i = 0; i < 3; i++) {
                        mma16816(acc[i][j], ahi[i], &bhi[jh * 2]);
                        mma16816(acc[i][j], ahi[i], &blo[jh * 2]);
                        mma16816(acc[i][j], alo[i], &bhi[jh * 2]);
                    }
                }
            }
        }

        // epilogue: store out chunk
#pragma unroll
        for (int i = 0; i < 3; i++) {
            int mlo = m0 + wm2 * 48 + i * 16 + (lane >> 2);
            int mhi = mlo + 8;
#pragma unroll
            for (int j = 0; j < 4; j++) {
                int t = t0 + wt2 * 32 + j * 8 + (lane & 3) * 2;
                if (mlo < Mm)
                    *(float2*)&out[((size_t)b * Mm + mlo) * Tt + t] =
                        make_float2(acc[i][j][0], acc[i][j][1]);
                if (mhi < Mm)
                    *(float2*)&out[((size_t)b * Mm + mhi) * Tt + t] =
                        make_float2(acc[i][j][2], acc[i][j][3]);
            }
        }
    }
}

// ---------------- launch ----------------
extern "C" void kernel_launch(void* const* d_in, const int* in_sizes, int n_in,
                              void* d_out, int out_size) {
    const float* x   = (const float*)d_in[0];  // [B, C, T]
    const float* pos = (const float*)d_in[1];  // [B, C, 2]
    const float* W   = (const float*)d_in[2];  // [M, G]
    float* out = (float*)d_out;                // [B, M, T]

    cudaFuncSetAttribute(fused_kernel, cudaFuncAttributeMaxDynamicSharedMemorySize, SM_TOTAL);

    precompute_kernel<<<(Bb * Cc + 255) / 256, 256>>>(pos);
    sbuild_kernel<<<(Bb * Gg * CP + 255) / 256, 256>>>();
    splitw_kernel<<<(MPAD * Gg + 255) / 256, 256>>>(W);
    fused_kernel<<<dim3(Tt / TT, Bb), 256, SM_TOTAL>>>(x, out);
}

// round 8
// speedup vs baseline: 4.0724x; 1.0498x over previous
#include <cuda_runtime.h>
#include <cuda_bf16.h>
#include <cstdint>

#define Bb 16
#define Cc 306
#define Tt 4096
#define Mm 270
#define Gg 64
#define CP 320            // padded channel count (5 chunks of 64)
#define MPAD 288          // 3 m-chunks of 96
#define TT 128            // t-tile per CTA

// ---------------- device scratch ----------------
__device__ __nv_bfloat16 d_Shi[Bb * Gg * CP];
__device__ __nv_bfloat16 d_Slo[Bb * Gg * CP];
__device__ __nv_bfloat16 d_Whi[MPAD * Gg];
__device__ __nv_bfloat16 d_Wlo[MPAD * Gg];

__device__ __forceinline__ uint32_t smem_u32(const void* p) {
    uint32_t a;
    asm("{ .reg .u64 t; cvta.to.shared.u64 t, %1; cvt.u32.u64 %0, t; }" : "=r"(a) : "l"(p));
    return a;
}
__device__ __forceinline__ void ldsm_x4(uint32_t* r, uint32_t addr) {
    asm volatile("ldmatrix.sync.aligned.m8n8.x4.shared.b16 {%0,%1,%2,%3}, [%4];"
                 : "=r"(r[0]), "=r"(r[1]), "=r"(r[2]), "=r"(r[3]) : "r"(addr));
}
__device__ __forceinline__ void ldsm_x4_t(uint32_t* r, uint32_t addr) {
    asm volatile("ldmatrix.sync.aligned.m8n8.x4.trans.shared.b16 {%0,%1,%2,%3}, [%4];"
                 : "=r"(r[0]), "=r"(r[1]), "=r"(r[2]), "=r"(r[3]) : "r"(addr));
}
__device__ __forceinline__ void mma16816(float* c, const uint32_t* a, const uint32_t* b) {
    asm volatile(
        "mma.sync.aligned.m16n8k16.row.col.f32.bf16.bf16.f32 "
        "{%0,%1,%2,%3}, {%4,%5,%6,%7}, {%8,%9}, {%0,%1,%2,%3};"
        : "+f"(c[0]), "+f"(c[1]), "+f"(c[2]), "+f"(c[3])
        : "r"(a[0]), "r"(a[1]), "r"(a[2]), "r"(a[3]), "r"(b[0]), "r"(b[1]));
}
__device__ __forceinline__ void cp16(uint32_t sm, const void* g) {
    asm volatile("cp.async.ca.shared.global [%0], [%1], 16;" :: "r"(sm), "l"(g));
}
#define CP_COMMIT() asm volatile("cp.async.commit_group;" ::: "memory")
#define CP_WAIT0()  asm volatile("cp.async.wait_group 0;" ::: "memory")

// ---------------- setup kernel (S build + W split, fused) ----------------
__global__ void setup_kernel(const float* __restrict__ pos, const float* __restrict__ W) {
    int i = blockIdx.x * 256 + threadIdx.x;
    if (i < Bb * Gg * CP) {
        int c = i % CP;
        int cell = (i / CP) % Gg;
        int b = i / (CP * Gg);
        float s = 0.0f;
        if (c < Cc) {
            float gp0 = (pos[(b * Cc + c) * 2 + 0] + 1.0f) * 4.0f;
            float gp1 = (pos[(b * Cc + c) * 2 + 1] + 1.0f) * 4.0f;
            float lo0 = floorf(gp0), lo1 = floorf(gp1);
            int il0 = min(7, max(0, (int)lo0)), il1 = min(7, max(0, (int)lo1));
            int ih0 = min(7, max(0, (int)ceilf(gp0))), ih1 = min(7, max(0, (int)ceilf(gp1)));
            float wh0 = gp0 - lo0, wl0 = 1.0f - wh0;
            float wh1 = gp1 - lo1, wl1 = 1.0f - wh1;
            if (il0 * 8 + il1 == cell) s += wl0 * wl1;
            if (il0 * 8 + ih1 == cell) s += wl0 * wh1;
            if (ih0 * 8 + il1 == cell) s += wh0 * wl1;
            if (ih0 * 8 + ih1 == cell) s += wh0 * wh1;
        }
        __nv_bfloat16 h = __float2bfloat16(s);
        d_Shi[i] = h;
        d_Slo[i] = __float2bfloat16(s - __bfloat162float(h));
    } else {
        int j = i - Bb * Gg * CP;
        if (j < MPAD * Gg) {
            float v = (j < Mm * Gg) ? W[j] : 0.0f;
            __nv_bfloat16 h = __float2bfloat16(v);
            d_Whi[j] = h;
            d_Wlo[j] = __float2bfloat16(v - __bfloat162float(h));
        }
    }
}

// ---------------- fused kernel (double-buffered, cp.async S/W) ----------------
#define A1PITCH 72
#define B1PITCH 136
#define GPITCH  136
#define WPITCH  72
#define SM_A1(buf) ((buf) * 18432)            // AHI +0, ALO +9216
#define SM_B1(buf) (36864 + (buf) * 34816)    // BHI +0, BLO +17408
#define SM_GV      106496                     // GVHI +0, GVLO +17408
#define SM_W(buf)  ((buf) * 27648)            // WHI +0, WLO +13824 (overlays A1/B1)
#define SM_TOTAL   141312

__global__ void __launch_bounds__(256, 1)
fused_kernel(const float* __restrict__ x, float* __restrict__ out) {
    extern __shared__ char smem[];
    const uint32_t sb = smem_u32(smem);
    const int tid = threadIdx.x;
    const int wid = tid >> 5;
    const int lane = tid & 31;

    const int t0 = blockIdx.x * TT;
    const int b  = blockIdx.y;

    const int arow = lane & 15;
    const int acol = (lane >> 4) * 8;

    // ======== phase 1: gv[64 x 128] = S_b @ x_tile ========
    const int wm1 = wid >> 2;
    const int wt1 = wid & 3;

    float gacc[2][4][4];
#pragma unroll
    for (int i = 0; i < 2; i++)
#pragma unroll
        for (int j = 0; j < 4; j++)
#pragma unroll
            for (int q = 0; q < 4; q++) gacc[i][j][q] = 0.0f;

    float4 xv[8];
    auto load_X = [&](int c0) {   // c0 = channel offset
#pragma unroll
        for (int it = 0; it < 8; it++) {
            int cg = c0 + wid + 8 * it;
            xv[it] = (cg < Cc)
                ? *(const float4*)(x + ((size_t)(b * Cc + cg)) * Tt + t0 + lane * 4)
                : make_float4(0.f, 0.f, 0.f, 0.f);
        }
    };
    auto cpS = [&](int c0, int buf) {
        const __nv_bfloat16* baseHi = d_Shi + (size_t)b * Gg * CP + c0;
        const __nv_bfloat16* baseLo = d_Slo + (size_t)b * Gg * CP + c0;
        uint32_t smA = sb + SM_A1(buf);
#pragma unroll
        for (int it = 0; it < 4; it++) {
            int idx = tid + it * 256;      // 0..1023
            int hl = idx >> 9;
            int r = (idx >> 3) & 63;
            int s = idx & 7;
            const __nv_bfloat16* g = (hl ? baseLo : baseHi) + r * CP + s * 8;
            cp16(smA + hl * 9216 + (r * A1PITCH + s * 8) * 2, g);
        }
    };
    auto stsX = [&](int buf) {
        char* base = smem + SM_B1(buf);
#pragma unroll
        for (int it = 0; it < 8; it++) {
            int r = wid + 8 * it;
            float4 v = xv[it];
            __nv_bfloat162 h0 = __floats2bfloat162_rn(v.x, v.y);
            __nv_bfloat162 h1 = __floats2bfloat162_rn(v.z, v.w);
            __nv_bfloat162 l0 = __floats2bfloat162_rn(
                v.x - __bfloat162float(__low2bfloat16(h0)),
                v.y - __bfloat162float(__high2bfloat16(h0)));
            __nv_bfloat162 l1 = __floats2bfloat162_rn(
                v.z - __bfloat162float(__low2bfloat16(h1)),
                v.w - __bfloat162float(__high2bfloat16(h1)));
            uint32_t boff = (r * B1PITCH + lane * 4) * 2;
            *(uint32_t*)(base + boff)             = *(uint32_t*)&h0;
            *(uint32_t*)(base + boff + 4)         = *(uint32_t*)&h1;
            *(uint32_t*)(base + 17408 + boff)     = *(uint32_t*)&l0;
            *(uint32_t*)(base + 17408 + boff + 4) = *(uint32_t*)&l1;
        }
    };
    auto mma1 = [&](int buf) {
        uint32_t baseA = sb + SM_A1(buf);
        uint32_t baseB = sb + SM_B1(buf);
#pragma unroll
        for (int ks = 0; ks < 4; ks++) {
            const int k0 = ks * 16;
            uint32_t ahi[2][4], alo[2][4];
#pragma unroll
            for (int i = 0; i < 2; i++) {
                uint32_t off = ((wm1 * 32 + i * 16 + arow) * A1PITCH + k0 + acol) * 2;
                ldsm_x4(ahi[i], baseA + off);
                ldsm_x4(alo[i], baseA + 9216 + off);
            }
#pragma unroll
            for (int j2 = 0; j2 < 2; j2++) {
                uint32_t off = ((k0 + arow) * B1PITCH + wt1 * 32 + j2 * 16 + acol) * 2;
                uint32_t bhi[4], blo[4];
                ldsm_x4_t(bhi, baseB + off);
                ldsm_x4_t(blo, baseB + 17408 + off);
#pragma unroll
                for (int jh = 0; jh < 2; jh++) {
                    int j = j2 * 2 + jh;
#pragma unroll
                    for (int i = 0; i < 2; i++) {
                        mma16816(gacc[i][j], ahi[i], &bhi[jh * 2]);
                        mma16816(gacc[i][j], ahi[i], &blo[jh * 2]);
                        mma16816(gacc[i][j], alo[i], &bhi[jh * 2]);
                    }
                }
            }
        }
    };

    // prologue: stage chunk 0, start LDG chunk 1 (channel offset 64)
    cpS(0, 0); CP_COMMIT();
    load_X(0);
    stsX(0);
    load_X(64);
    CP_WAIT0();
    __syncthreads();

    for (int kc = 0; kc < 5; kc++) {
        const int cur = kc & 1, nxt = cur ^ 1;
        if (kc < 4) { cpS((kc + 1) * 64, nxt); CP_COMMIT(); }
        mma1(cur);
        if (kc < 4) {
            stsX(nxt);                             // x(kc+1): LDGs landed during MMA
            if (kc < 3) load_X((kc + 2) * 64);     // next LDGs fly under next MMA
            CP_WAIT0();
        }
        __syncthreads();
    }

    // ======== phase 2 prologue: W(0) cp.async overlapped with gv split ========
    auto cpW = [&](int m0, int buf) {
        uint32_t smW = sb + SM_W(buf);
#pragma unroll
        for (int it = 0; it < 6; it++) {
            int idx = tid + it * 256;      // 0..1535
            int hl = idx >= 768;
            int j = hl ? idx - 768 : idx;
            int r = j >> 3;
            int s = j & 7;
            const __nv_bfloat16* g = (hl ? d_Wlo : d_Whi) + (m0 + r) * Gg + s * 8;
            cp16(smW + hl * 13824 + (r * WPITCH + s * 8) * 2, g);
        }
    };
    cpW(0, 0); CP_COMMIT();

    // gv split into region Y
#pragma unroll
    for (int i = 0; i < 2; i++) {
        int r0 = wm1 * 32 + i * 16 + (lane >> 2);
        int r1 = r0 + 8;
#pragma unroll
        for (int j = 0; j < 4; j++) {
            int t = wt1 * 32 + j * 8 + (lane & 3) * 2;
            __nv_bfloat162 h0 = __floats2bfloat162_rn(gacc[i][j][0], gacc[i][j][1]);
            __nv_bfloat162 l0 = __floats2bfloat162_rn(
                gacc[i][j][0] - __bfloat162float(__low2bfloat16(h0)),
                gacc[i][j][1] - __bfloat162float(__high2bfloat16(h0)));
            __nv_bfloat162 h1 = __floats2bfloat162_rn(gacc[i][j][2], gacc[i][j][3]);
            __nv_bfloat162 l1 = __floats2bfloat162_rn(
                gacc[i][j][2] - __bfloat162float(__low2bfloat16(h1)),
                gacc[i][j][3] - __bfloat162float(__high2bfloat16(h1)));
            *(uint32_t*)(smem + SM_GV + (r0 * GPITCH + t) * 2)         = *(uint32_t*)&h0;
            *(uint32_t*)(smem + SM_GV + 17408 + (r0 * GPITCH + t) * 2) = *(uint32_t*)&l0;
            *(uint32_t*)(smem + SM_GV + (r1 * GPITCH + t) * 2)         = *(uint32_t*)&h1;
            *(uint32_t*)(smem + SM_GV + 17408 + (r1 * GPITCH + t) * 2) = *(uint32_t*)&l1;
        }
    }
    CP_WAIT0();
    __syncthreads();

    // ======== phase 2: out = W_chunk @ gv, W double-buffered ========
    const int wm2 = wid >> 2;
    const int wt2 = wid & 3;

    for (int mc = 0; mc < 3; mc++) {
        const int cur = mc & 1, nxt = cur ^ 1;
        if (mc < 2) { cpW((mc + 1) * 96, nxt); CP_COMMIT(); }

        float acc[3][4][4];
#pragma unroll
        for (int i = 0; i < 3; i++)
#pragma unroll
            for (int j = 0; j < 4; j++)
#pragma unroll
                for (int q = 0; q < 4; q++) acc[i][j][q] = 0.0f;

        uint32_t baseW = sb + SM_W(cur);
#pragma unroll
        for (int ks = 0; ks < 4; ks++) {
            const int k0 = ks * 16;
            uint32_t ahi[3][4], alo[3][4];
#pragma unroll
            for (int i = 0; i < 3; i++) {
                uint32_t off = ((wm2 * 48 + i * 16 + arow) * WPITCH + k0 + acol) * 2;
                ldsm_x4(ahi[i], baseW + off);
                ldsm_x4(alo[i], baseW + 13824 + off);
            }
#pragma unroll
            for (int j2 = 0; j2 < 2; j2++) {
                uint32_t off = ((k0 + arow) * GPITCH + wt2 * 32 + j2 * 16 + acol) * 2;
                uint32_t bhi[4], blo[4];
                ldsm_x4_t(bhi, sb + SM_GV + off);
                ldsm_x4_t(blo, sb + SM_GV + 17408 + off);
#pragma unroll
                for (int jh = 0; jh < 2; jh++) {
                    int j = j2 * 2 + jh;
#pragma unroll
                    for (int i = 0; i < 3; i++) {
                        mma16816(acc[i][j], ahi[i], &bhi[jh * 2]);
                        mma16816(acc[i][j], ahi[i], &blo[jh * 2]);
                        mma16816(acc[i][j], alo[i], &bhi[jh * 2]);
                    }
                }
            }
        }

        // epilogue: store out chunk
        const int m0 = mc * 96;
#pragma unroll
        for (int i = 0; i < 3; i++) {
            int mlo = m0 + wm2 * 48 + i * 16 + (lane >> 2);
            int mhi = mlo + 8;
#pragma unroll
            for (int j = 0; j < 4; j++) {
                int t = t0 + wt2 * 32 + j * 8 + (lane & 3) * 2;
                if (mlo < Mm)
                    *(float2*)&out[((size_t)b * Mm + mlo) * Tt + t] =
                        make_float2(acc[i][j][0], acc[i][j][1]);
                if (mhi < Mm)
                    *(float2*)&out[((size_t)b * Mm + mhi) * Tt + t] =
                        make_float2(acc[i][j][2], acc[i][j][3]);
            }
        }
        if (mc < 2) {
            CP_WAIT0();
            __syncthreads();
        }
    }
}

// ---------------- launch ----------------
extern "C" void kernel_launch(void* const* d_in, const int* in_sizes, int n_in,
                              void* d_out, int out_size) {
    const float* x   = (const float*)d_in[0];  // [B, C, T]
    const float* pos = (const float*)d_in[1];  // [B, C, 2]
    const float* W   = (const float*)d_in[2];  // [M, G]
    float* out = (float*)d_out;                // [B, M, T]

    cudaFuncSetAttribute(fused_kernel, cudaFuncAttributeMaxDynamicSharedMemorySize, SM_TOTAL);

    const int njobs = Bb * Gg * CP + MPAD * Gg;
    setup_kernel<<<(njobs + 255) / 256, 256>>>(pos, W);
    fused_kernel<<<dim3(Tt / TT, Bb), 256, SM_TOTAL>>>(x, out);
}